// round 13
// baseline (speedup 1.0000x reference)
#include <cuda_runtime.h>
#include <cuda_bf16.h>

#define NN 50000
#define NE 600000
#define DD 128
#define MT2 64            // nodes per CTA (half tile)
#define NT2 782           // 64-row tiles covering 50048 rows
#define LDA 136           // padded smem row (bf16 units): 272B, conflict-free ldmatrix
#define NSB 49            // scan blocks: 49 * 1024 >= NN

// ---------------- scratch (device globals; no allocation allowed) ----------------
// counters zero at module load; re-zeroed inside k_fill each call (deterministic)
__device__ int   g_out_cnt[NN];
__device__ int   g_in_cnt[NN];
__device__ int   g_row_off[NN + 1];
__device__ int   g_cursor[NN];
__device__ int   g_csr_src[NE];
__device__ float g_src_norm[NN];
__device__ float g_dst_norm[NN];
__device__ float g_h0[NN * DD];    // holds src_norm-prescaled h for next layer
__device__ float g_h1[NN * DD];
// bf16 split of W (k x n row-major), per layer
__device__ __align__(16) unsigned short g_wh16[4 * DD * DD];
__device__ __align__(16) unsigned short g_wl16[4 * DD * DD];

// ---------------- PTX helpers (base sm_100 compatible only!) ----------------
__device__ __forceinline__ unsigned s2u(const void* p) {
    unsigned r;
    asm("{ .reg .u64 t; cvta.to.shared.u64 t, %1; cvt.u32.u64 %0, t; }" : "=r"(r) : "l"(p));
    return r;
}
#define LDSM_X4(r, a)                                                         \
    asm volatile("ldmatrix.sync.aligned.m8n8.x4.shared.b16 {%0,%1,%2,%3}, [%4];" \
        : "=r"((r)[0]), "=r"((r)[1]), "=r"((r)[2]), "=r"((r)[3]) : "r"(a))
#define LDSM_X4T(r, a)                                                        \
    asm volatile("ldmatrix.sync.aligned.m8n8.x4.trans.shared.b16 {%0,%1,%2,%3}, [%4];" \
        : "=r"((r)[0]), "=r"((r)[1]), "=r"((r)[2]), "=r"((r)[3]) : "r"(a))
#define MMA16816(c, a, b0_, b1_)                                              \
    asm volatile("mma.sync.aligned.m16n8k16.row.col.f32.bf16.bf16.f32 "       \
        "{%0,%1,%2,%3},{%4,%5,%6,%7},{%8,%9},{%0,%1,%2,%3};"                  \
        : "+f"((c)[0]), "+f"((c)[1]), "+f"((c)[2]), "+f"((c)[3])              \
        : "r"((a)[0]), "r"((a)[1]), "r"((a)[2]), "r"((a)[3]), "r"(b0_), "r"(b1_))

// ---------------- launch 0: degree count + W split (fused) ----------------
__global__ void k_count_w(const int* __restrict__ src, const int* __restrict__ dst,
                          const float* __restrict__ W) {
    int e = blockIdx.x * blockDim.x + threadIdx.x;
    if (e < NE) {
        atomicAdd(&g_out_cnt[src[e]], 1);
        atomicAdd(&g_in_cnt[dst[e]], 1);
    }
    if (e < 4 * DD * DD) {
        float v = __ldg(W + e);
        __nv_bfloat16 hi = __float2bfloat16(v);
        float lo = v - __bfloat162float(hi);
        g_wh16[e] = __bfloat16_as_ushort(hi);
        g_wl16[e] = __bfloat16_as_ushort(__float2bfloat16(lo));
    }
}

// ---------------- launch 1: one-kernel scan (self-computed base) + norms ----------
__global__ __launch_bounds__(1024) void k_scan2() {
    __shared__ int sd[1024];
    __shared__ int sbase;
    int t = threadIdx.x, b = blockIdx.x;
    int i = b * 1024 + t;
    int incnt = (i < NN) ? g_in_cnt[i] : 0;
    int part = 0;
    for (int k = t; k < b * 1024; k += 1024) part += g_in_cnt[k];
    sd[t] = part;
    __syncthreads();
#pragma unroll
    for (int s = 512; s > 0; s >>= 1) {
        if (t < s) sd[t] += sd[t + s];
        __syncthreads();
    }
    if (t == 0) sbase = sd[0];
    __syncthreads();
    int base = sbase;
    __syncthreads();
    sd[t] = incnt;
    __syncthreads();
#pragma unroll
    for (int off = 1; off < 1024; off <<= 1) {
        int v = (t >= off) ? sd[t - off] : 0;
        __syncthreads();
        sd[t] += v;
        __syncthreads();
    }
    int excl = sd[t] - incnt;
    if (i < NN) {
        int o = base + excl;
        g_row_off[i] = o;
        g_cursor[i]  = o;
        g_src_norm[i] = rsqrtf((float)max(g_out_cnt[i], 1));
        g_dst_norm[i] = rsqrtf((float)max(incnt, 1));
    }
    if (b == NSB - 1 && t == 1023) g_row_off[NN] = base + sd[1023];
}

// ---------------- launch 2: CSR fill + counter re-zero ----------------
__global__ void k_fill(const int* __restrict__ src, const int* __restrict__ dst) {
    int e = blockIdx.x * blockDim.x + threadIdx.x;
    if (e < NE) {
        int d = dst[e];
        int p = atomicAdd(&g_cursor[d], 1);
        g_csr_src[p] = src[e];
    }
    if (e < NN) { g_out_cnt[e] = 0; g_in_cnt[e] = 0; }
}

// ---------------- fused aggregate + GEMM, 2 CTAs/SM for phase overlap ------------
// CTA t: nodes [t*64, t*64+64). 512 threads (16 warps), 2 CTAs/SM.
// Phase 1: warp w aggregates nodes w*4..w*4+3 (4 independent accumulators).
// Phase 2: warp grid 2m x 8n; per-warp 32rows x 16cols, 2x2 mma tile, 3-term split.
// smem/CTA: Wh|Wl (DD*LDA each) + Ah|Al (MT2*LDA each) = 104448 B -> 2 CTAs/SM.
#define FSMEM ((2 * DD + 2 * MT2) * LDA * 2)

__global__ __launch_bounds__(512, 2) void k_fused(
        const float* __restrict__ ext, int sel, int layer,
        const float* __restrict__ bias, float* __restrict__ ext_out, int out_sel) {
    extern __shared__ unsigned short smx[];
    unsigned short* sWh = smx;
    unsigned short* sWl = smx + DD * LDA;
    unsigned short* sAh = smx + 2 * DD * LDA;
    unsigned short* sAl = smx + 2 * DD * LDA + MT2 * LDA;

    int tid = threadIdx.x, lane = tid & 31, w = tid >> 5;
    int t = blockIdx.x;
    const float4* h4 = (const float4*)(sel == 0 ? ext : (sel == 1 ? g_h0 : g_h1));
    float* out = out_sel == 0 ? ext_out : (out_sel == 1 ? g_h0 : g_h1);

    // stage W (512 threads x 4 uint4 each per array)
    {
        const uint4* w_h = (const uint4*)(g_wh16 + layer * DD * DD);
        const uint4* w_l = (const uint4*)(g_wl16 + layer * DD * DD);
#pragma unroll
        for (int i = 0; i < 4; i++) {
            int li = tid + i * 512;
            int r = li >> 4, c = li & 15;
            int d = r * LDA + c * 8;
            *(uint4*)&sWh[d] = w_h[li];
            *(uint4*)&sWl[d] = w_l[li];
        }
    }

    // ---------------- phase 1: aggregate 4 nodes per warp (rows 0..63) ----------
#pragma unroll
    for (int q = 0; q < 4; q++) {
        int r = w * 4 + q;              // local row 0..63
        int gw = t * MT2 + r;
        float4 acc = make_float4(0.f, 0.f, 0.f, 0.f);
        if (gw < NN) {
            int beg = __ldg(&g_row_off[gw]), end = __ldg(&g_row_off[gw + 1]);
            int j = beg;
            float4 A0 = make_float4(0.f, 0.f, 0.f, 0.f);
            float4 A1 = make_float4(0.f, 0.f, 0.f, 0.f);
            float4 A2 = make_float4(0.f, 0.f, 0.f, 0.f);
            float4 A3 = make_float4(0.f, 0.f, 0.f, 0.f);
            if (sel == 0) {
                for (; j + 4 <= end; j += 4) {
                    int s0 = __ldg(&g_csr_src[j]),     s1 = __ldg(&g_csr_src[j + 1]);
                    int s2 = __ldg(&g_csr_src[j + 2]), s3 = __ldg(&g_csr_src[j + 3]);
                    float n0 = __ldg(&g_src_norm[s0]), n1 = __ldg(&g_src_norm[s1]);
                    float n2 = __ldg(&g_src_norm[s2]), n3 = __ldg(&g_src_norm[s3]);
                    float4 v0 = __ldg(&h4[s0 * 32 + lane]);
                    float4 v1 = __ldg(&h4[s1 * 32 + lane]);
                    float4 v2 = __ldg(&h4[s2 * 32 + lane]);
                    float4 v3 = __ldg(&h4[s3 * 32 + lane]);
                    A0.x = fmaf(v0.x, n0, A0.x); A0.y = fmaf(v0.y, n0, A0.y);
                    A0.z = fmaf(v0.z, n0, A0.z); A0.w = fmaf(v0.w, n0, A0.w);
                    A1.x = fmaf(v1.x, n1, A1.x); A1.y = fmaf(v1.y, n1, A1.y);
                    A1.z = fmaf(v1.z, n1, A1.z); A1.w = fmaf(v1.w, n1, A1.w);
                    A2.x = fmaf(v2.x, n2, A2.x); A2.y = fmaf(v2.y, n2, A2.y);
                    A2.z = fmaf(v2.z, n2, A2.z); A2.w = fmaf(v2.w, n2, A2.w);
                    A3.x = fmaf(v3.x, n3, A3.x); A3.y = fmaf(v3.y, n3, A3.y);
                    A3.z = fmaf(v3.z, n3, A3.z); A3.w = fmaf(v3.w, n3, A3.w);
                }
                for (; j < end; j++) {
                    int s0 = __ldg(&g_csr_src[j]);
                    float n0 = __ldg(&g_src_norm[s0]);
                    float4 v0 = __ldg(&h4[s0 * 32 + lane]);
                    A0.x = fmaf(v0.x, n0, A0.x); A0.y = fmaf(v0.y, n0, A0.y);
                    A0.z = fmaf(v0.z, n0, A0.z); A0.w = fmaf(v0.w, n0, A0.w);
                }
            } else {
                for (; j + 4 <= end; j += 4) {
                    int s0 = __ldg(&g_csr_src[j]),     s1 = __ldg(&g_csr_src[j + 1]);
                    int s2 = __ldg(&g_csr_src[j + 2]), s3 = __ldg(&g_csr_src[j + 3]);
                    float4 v0 = __ldg(&h4[s0 * 32 + lane]);
                    float4 v1 = __ldg(&h4[s1 * 32 + lane]);
                    float4 v2 = __ldg(&h4[s2 * 32 + lane]);
                    float4 v3 = __ldg(&h4[s3 * 32 + lane]);
                    A0.x += v0.x; A0.y += v0.y; A0.z += v0.z; A0.w += v0.w;
                    A1.x += v1.x; A1.y += v1.y; A1.z += v1.z; A1.w += v1.w;
                    A2.x += v2.x; A2.y += v2.y; A2.z += v2.z; A2.w += v2.w;
                    A3.x += v3.x; A3.y += v3.y; A3.z += v3.z; A3.w += v3.w;
                }
                for (; j < end; j++) {
                    int s0 = __ldg(&g_csr_src[j]);
                    float4 v0 = __ldg(&h4[s0 * 32 + lane]);
                    A0.x += v0.x; A0.y += v0.y; A0.z += v0.z; A0.w += v0.w;
                }
            }
            float dn = __ldg(&g_dst_norm[gw]);
            acc.x = ((A0.x + A1.x) + (A2.x + A3.x)) * dn;
            acc.y = ((A0.y + A1.y) + (A2.y + A3.y)) * dn;
            acc.z = ((A0.z + A1.z) + (A2.z + A3.z)) * dn;
            acc.w = ((A0.w + A1.w) + (A2.w + A3.w)) * dn;
        }
        // split to bf16 hi/lo, store to smem in ldmatrix layout
        __nv_bfloat16 hx = __float2bfloat16(acc.x), hy = __float2bfloat16(acc.y);
        __nv_bfloat16 hz = __float2bfloat16(acc.z), hw = __float2bfloat16(acc.w);
        ushort4 vh, vl;
        vh.x = __bfloat16_as_ushort(hx); vh.y = __bfloat16_as_ushort(hy);
        vh.z = __bfloat16_as_ushort(hz); vh.w = __bfloat16_as_ushort(hw);
        vl.x = __bfloat16_as_ushort(__float2bfloat16(acc.x - __bfloat162float(hx)));
        vl.y = __bfloat16_as_ushort(__float2bfloat16(acc.y - __bfloat162float(hy)));
        vl.z = __bfloat16_as_ushort(__float2bfloat16(acc.z - __bfloat162float(hz)));
        vl.w = __bfloat16_as_ushort(__float2bfloat16(acc.w - __bfloat162float(hw)));
        *(ushort4*)&sAh[r * LDA + lane * 4] = vh;
        *(ushort4*)&sAl[r * LDA + lane * 4] = vl;
    }
    __syncthreads();

    // ---------------- phase 2: 3-term mma, warp grid 2m x 8n --------------------
    int mw = w & 1, nw = w >> 1;     // 2 m-groups (32 rows) x 8 n-groups (16 cols)

    float acc2[2][2][4];
#pragma unroll
    for (int mt = 0; mt < 2; mt++)
#pragma unroll
        for (int nt = 0; nt < 2; nt++)
#pragma unroll
            for (int q = 0; q < 4; q++) acc2[mt][nt][q] = 0.f;

    unsigned aH[2], aL[2];
#pragma unroll
    for (int mt = 0; mt < 2; mt++) {
        int r = mw * 32 + mt * 16 + (lane & 15);
        aH[mt] = s2u(&sAh[r * LDA + (lane >> 4) * 8]);
        aL[mt] = s2u(&sAl[r * LDA + (lane >> 4) * 8]);
    }
    unsigned bB = (lane < 16) ? s2u(&sWh[(lane & 15) * LDA + nw * 16])
                              : s2u(&sWl[(lane & 15) * LDA + nw * 16]);

#pragma unroll
    for (int ks = 0; ks < 8; ks++) {
        unsigned ah[2][4], al[2][4];
#pragma unroll
        for (int mt = 0; mt < 2; mt++) {
            LDSM_X4(ah[mt], aH[mt] + ks * 32);
            LDSM_X4(al[mt], aL[mt] + ks * 32);
        }
#pragma unroll
        for (int nt = 0; nt < 2; nt++) {
            unsigned b[4];                 // b[0..1]=Wh frag, b[2..3]=Wl frag
            LDSM_X4T(b, bB + ks * 16 * LDA * 2 + nt * 16);
#pragma unroll
            for (int mt = 0; mt < 2; mt++) {
                MMA16816(acc2[mt][nt], ah[mt], b[0], b[1]);
                MMA16816(acc2[mt][nt], ah[mt], b[2], b[3]);
                MMA16816(acc2[mt][nt], al[mt], b[0], b[1]);
            }
        }
    }

    // epilogue (prescale by src_norm for non-final layers)
#pragma unroll
    for (int mt = 0; mt < 2; mt++) {
        int r0 = t * MT2 + mw * 32 + mt * 16 + (lane >> 2);
        int r1 = r0 + 8;
        float sn0 = 1.f, sn1 = 1.f;
        if (out_sel != 0) {
            if (r0 < NN) sn0 = __ldg(&g_src_norm[r0]);
            if (r1 < NN) sn1 = __ldg(&g_src_norm[r1]);
        }
#pragma unroll
        for (int nt = 0; nt < 2; nt++) {
            int col = nw * 16 + nt * 8 + (lane & 3) * 2;
            float2 bb = *(const float2*)&bias[col];
            if (r0 < NN) {
                float2 v; v.x = (acc2[mt][nt][0] + bb.x) * sn0; v.y = (acc2[mt][nt][1] + bb.y) * sn0;
                *(float2*)&out[(size_t)r0 * DD + col] = v;
            }
            if (r1 < NN) {
                float2 v; v.x = (acc2[mt][nt][2] + bb.x) * sn1; v.y = (acc2[mt][nt][3] + bb.y) * sn1;
                *(float2*)&out[(size_t)r1 * DD + col] = v;
            }
        }
    }
}

// ---------------- launch ----------------
extern "C" void kernel_launch(void* const* d_in, const int* in_sizes, int n_in,
                              void* d_out, int out_size) {
    const float* feat = (const float*)d_in[0];
    const int*   src  = (const int*)d_in[1];
    const int*   dst  = (const int*)d_in[2];
    const float* W    = (const float*)d_in[3];
    const float* b    = (const float*)d_in[4];
    float* out = (float*)d_out;

    cudaFuncSetAttribute(k_fused, cudaFuncAttributeMaxDynamicSharedMemorySize, FSMEM);

    const int TB = 256;
    k_count_w<<<(NE + TB - 1) / TB, TB>>>(src, dst, W);    // 0
    k_scan2<<<NSB, 1024>>>();                              // 1
    k_fill<<<(NE + TB - 1) / TB, TB>>>(src, dst);          // 2

    k_fused<<<NT2, 512, FSMEM>>>(feat, 0, 0, b + 0 * DD, nullptr, 1);   // 3 <-- profiled
    k_fused<<<NT2, 512, FSMEM>>>(nullptr, 1, 1, b + 1 * DD, nullptr, 2);
    k_fused<<<NT2, 512, FSMEM>>>(nullptr, 2, 2, b + 2 * DD, nullptr, 1);
    k_fused<<<NT2, 512, FSMEM>>>(nullptr, 1, 3, b + 3 * DD, out, 0);
}

// round 14
// speedup vs baseline: 1.1065x; 1.1065x over previous
#include <cuda_runtime.h>
#include <cuda_bf16.h>

#define NN 50000
#define NE 600000
#define DD 128
#define NT 391            // 128-row tiles covering 50048 rows
#define LDA 136           // padded smem row (bf16 units): 272B, conflict-free ldmatrix
#define NSB 49            // scan blocks: 49 * 1024 >= NN

// ---------------- scratch (device globals; no allocation allowed) ----------------
// counters zero at module load; re-zeroed inside k_fill each call (deterministic)
__device__ int   g_out_cnt[NN];
__device__ int   g_in_cnt[NN];
__device__ int   g_row_off[NN + 1];
__device__ int   g_cursor[NN];
__device__ int   g_csr_src[NE];
__device__ float g_src_norm[NN];
__device__ float g_dst_norm[NN];
__device__ float g_h0[NN * DD];    // holds src_norm-prescaled h for next layer
__device__ float g_h1[NN * DD];
// bf16 split of W (k x n row-major), per layer
__device__ __align__(16) unsigned short g_wh16[4 * DD * DD];
__device__ __align__(16) unsigned short g_wl16[4 * DD * DD];

// ---------------- PTX helpers (base sm_100 compatible only!) ----------------
__device__ __forceinline__ unsigned s2u(const void* p) {
    unsigned r;
    asm("{ .reg .u64 t; cvta.to.shared.u64 t, %1; cvt.u32.u64 %0, t; }" : "=r"(r) : "l"(p));
    return r;
}
#define LDSM_X4(r, a)                                                         \
    asm volatile("ldmatrix.sync.aligned.m8n8.x4.shared.b16 {%0,%1,%2,%3}, [%4];" \
        : "=r"((r)[0]), "=r"((r)[1]), "=r"((r)[2]), "=r"((r)[3]) : "r"(a))
#define LDSM_X4T(r, a)                                                        \
    asm volatile("ldmatrix.sync.aligned.m8n8.x4.trans.shared.b16 {%0,%1,%2,%3}, [%4];" \
        : "=r"((r)[0]), "=r"((r)[1]), "=r"((r)[2]), "=r"((r)[3]) : "r"(a))
#define MMA16816(c, a, b0_, b1_)                                              \
    asm volatile("mma.sync.aligned.m16n8k16.row.col.f32.bf16.bf16.f32 "       \
        "{%0,%1,%2,%3},{%4,%5,%6,%7},{%8,%9},{%0,%1,%2,%3};"                  \
        : "+f"((c)[0]), "+f"((c)[1]), "+f"((c)[2]), "+f"((c)[3])              \
        : "r"((a)[0]), "r"((a)[1]), "r"((a)[2]), "r"((a)[3]), "r"(b0_), "r"(b1_))

// ---------------- launch 0: degree count + W split (fused) ----------------
__global__ void k_count_w(const int* __restrict__ src, const int* __restrict__ dst,
                          const float* __restrict__ W) {
    int e = blockIdx.x * blockDim.x + threadIdx.x;
    if (e < NE) {
        atomicAdd(&g_out_cnt[src[e]], 1);
        atomicAdd(&g_in_cnt[dst[e]], 1);
    }
    if (e < 4 * DD * DD) {
        float v = __ldg(W + e);
        __nv_bfloat16 hi = __float2bfloat16(v);
        float lo = v - __bfloat162float(hi);
        g_wh16[e] = __bfloat16_as_ushort(hi);
        g_wl16[e] = __bfloat16_as_ushort(__float2bfloat16(lo));
    }
}

// ---------------- launch 1: one-kernel scan (self-computed base) + norms ----------
__global__ __launch_bounds__(1024) void k_scan2() {
    __shared__ int sd[1024];
    __shared__ int sbase;
    int t = threadIdx.x, b = blockIdx.x;
    int i = b * 1024 + t;
    int incnt = (i < NN) ? g_in_cnt[i] : 0;
    int part = 0;
    for (int k = t; k < b * 1024; k += 1024) part += g_in_cnt[k];
    sd[t] = part;
    __syncthreads();
#pragma unroll
    for (int s = 512; s > 0; s >>= 1) {
        if (t < s) sd[t] += sd[t + s];
        __syncthreads();
    }
    if (t == 0) sbase = sd[0];
    __syncthreads();
    int base = sbase;
    __syncthreads();
    sd[t] = incnt;
    __syncthreads();
#pragma unroll
    for (int off = 1; off < 1024; off <<= 1) {
        int v = (t >= off) ? sd[t - off] : 0;
        __syncthreads();
        sd[t] += v;
        __syncthreads();
    }
    int excl = sd[t] - incnt;
    if (i < NN) {
        int o = base + excl;
        g_row_off[i] = o;
        g_cursor[i]  = o;
        g_src_norm[i] = rsqrtf((float)max(g_out_cnt[i], 1));
        g_dst_norm[i] = rsqrtf((float)max(incnt, 1));
    }
    if (b == NSB - 1 && t == 1023) g_row_off[NN] = base + sd[1023];
}

// ---------------- launch 2: CSR fill + counter re-zero ----------------
__global__ void k_fill(const int* __restrict__ src, const int* __restrict__ dst) {
    int e = blockIdx.x * blockDim.x + threadIdx.x;
    if (e < NE) {
        int d = dst[e];
        int p = atomicAdd(&g_cursor[d], 1);
        g_csr_src[p] = src[e];
    }
    if (e < NN) { g_out_cnt[e] = 0; g_in_cnt[e] = 0; }
}

// ---------------- fused aggregate + GEMM (R12 shape + index prefetch) ------------
// CTA t: nodes [t*128, t*128+128). 1024 threads (32 warps), 1 CTA/SM.
// Phase 1: warp w aggregates nodes w*4..w*4+3; CSR indices for the NEXT quad are
//          prefetched before the current quad's row loads (hides idx latency).
// Phase 2: 32 warps mma, warp tile 32m x 16n, 3-term bf16 split.
#define FSMEM (4 * DD * LDA * 2)

__global__ __launch_bounds__(1024, 1) void k_fused(
        const float* __restrict__ ext, int sel, int layer,
        const float* __restrict__ bias, float* __restrict__ ext_out, int out_sel) {
    extern __shared__ unsigned short smx[];
    unsigned short* sWh = smx;
    unsigned short* sWl = smx + DD * LDA;
    unsigned short* sAh = smx + 2 * DD * LDA;
    unsigned short* sAl = smx + 3 * DD * LDA;

    int tid = threadIdx.x, lane = tid & 31, w = tid >> 5;
    int t = blockIdx.x;
    const float4* h4 = (const float4*)(sel == 0 ? ext : (sel == 1 ? g_h0 : g_h1));
    float* out = out_sel == 0 ? ext_out : (out_sel == 1 ? g_h0 : g_h1);

    // stage W (1024 threads x 2 uint4 each per array)
    {
        const uint4* w_h = (const uint4*)(g_wh16 + layer * DD * DD);
        const uint4* w_l = (const uint4*)(g_wl16 + layer * DD * DD);
#pragma unroll
        for (int i = 0; i < 2; i++) {
            int li = tid + i * 1024;
            int r = li >> 4, c = li & 15;
            int d = r * LDA + c * 8;
            *(uint4*)&sWh[d] = w_h[li];
            *(uint4*)&sWl[d] = w_l[li];
        }
    }

    // ---------------- phase 1: aggregate 4 nodes per warp, idx prefetch ---------
#pragma unroll
    for (int q = 0; q < 4; q++) {
        int r = w * 4 + q;              // local row 0..127
        int gw = t * DD + r;
        float4 acc = make_float4(0.f, 0.f, 0.f, 0.f);
        if (gw < NN) {
            int beg = __ldg(&g_row_off[gw]), end = __ldg(&g_row_off[gw + 1]);
            int j = beg;
            float4 A0 = make_float4(0.f, 0.f, 0.f, 0.f);
            float4 A1 = make_float4(0.f, 0.f, 0.f, 0.f);
            float4 A2 = make_float4(0.f, 0.f, 0.f, 0.f);
            float4 A3 = make_float4(0.f, 0.f, 0.f, 0.f);
            int s0 = 0, s1 = 0, s2 = 0, s3 = 0;
            bool have = (j + 4 <= end);
            if (have) {
                s0 = __ldg(&g_csr_src[j]);     s1 = __ldg(&g_csr_src[j + 1]);
                s2 = __ldg(&g_csr_src[j + 2]); s3 = __ldg(&g_csr_src[j + 3]);
            }
            if (sel == 0) {
                for (; j + 8 <= end; j += 4) {
                    int t0 = __ldg(&g_csr_src[j + 4]); int t1 = __ldg(&g_csr_src[j + 5]);
                    int t2 = __ldg(&g_csr_src[j + 6]); int t3 = __ldg(&g_csr_src[j + 7]);
                    float n0 = __ldg(&g_src_norm[s0]), n1 = __ldg(&g_src_norm[s1]);
                    float n2 = __ldg(&g_src_norm[s2]), n3 = __ldg(&g_src_norm[s3]);
                    float4 v0 = __ldg(&h4[s0 * 32 + lane]);
                    float4 v1 = __ldg(&h4[s1 * 32 + lane]);
                    float4 v2 = __ldg(&h4[s2 * 32 + lane]);
                    float4 v3 = __ldg(&h4[s3 * 32 + lane]);
                    A0.x = fmaf(v0.x, n0, A0.x); A0.y = fmaf(v0.y, n0, A0.y);
                    A0.z = fmaf(v0.z, n0, A0.z); A0.w = fmaf(v0.w, n0, A0.w);
                    A1.x = fmaf(v1.x, n1, A1.x); A1.y = fmaf(v1.y, n1, A1.y);
                    A1.z = fmaf(v1.z, n1, A1.z); A1.w = fmaf(v1.w, n1, A1.w);
                    A2.x = fmaf(v2.x, n2, A2.x); A2.y = fmaf(v2.y, n2, A2.y);
                    A2.z = fmaf(v2.z, n2, A2.z); A2.w = fmaf(v2.w, n2, A2.w);
                    A3.x = fmaf(v3.x, n3, A3.x); A3.y = fmaf(v3.y, n3, A3.y);
                    A3.z = fmaf(v3.z, n3, A3.z); A3.w = fmaf(v3.w, n3, A3.w);
                    s0 = t0; s1 = t1; s2 = t2; s3 = t3;
                }
                if (have) {
                    float n0 = __ldg(&g_src_norm[s0]), n1 = __ldg(&g_src_norm[s1]);
                    float n2 = __ldg(&g_src_norm[s2]), n3 = __ldg(&g_src_norm[s3]);
                    float4 v0 = __ldg(&h4[s0 * 32 + lane]);
                    float4 v1 = __ldg(&h4[s1 * 32 + lane]);
                    float4 v2 = __ldg(&h4[s2 * 32 + lane]);
                    float4 v3 = __ldg(&h4[s3 * 32 + lane]);
                    A0.x = fmaf(v0.x, n0, A0.x); A0.y = fmaf(v0.y, n0, A0.y);
                    A0.z = fmaf(v0.z, n0, A0.z); A0.w = fmaf(v0.w, n0, A0.w);
                    A1.x = fmaf(v1.x, n1, A1.x); A1.y = fmaf(v1.y, n1, A1.y);
                    A1.z = fmaf(v1.z, n1, A1.z); A1.w = fmaf(v1.w, n1, A1.w);
                    A2.x = fmaf(v2.x, n2, A2.x); A2.y = fmaf(v2.y, n2, A2.y);
                    A2.z = fmaf(v2.z, n2, A2.z); A2.w = fmaf(v2.w, n2, A2.w);
                    A3.x = fmaf(v3.x, n3, A3.x); A3.y = fmaf(v3.y, n3, A3.y);
                    A3.z = fmaf(v3.z, n3, A3.z); A3.w = fmaf(v3.w, n3, A3.w);
                    j += 4;
                }
                for (; j < end; j++) {
                    int u = __ldg(&g_csr_src[j]);
                    float n0 = __ldg(&g_src_norm[u]);
                    float4 v0 = __ldg(&h4[u * 32 + lane]);
                    A0.x = fmaf(v0.x, n0, A0.x); A0.y = fmaf(v0.y, n0, A0.y);
                    A0.z = fmaf(v0.z, n0, A0.z); A0.w = fmaf(v0.w, n0, A0.w);
                }
            } else {
                for (; j + 8 <= end; j += 4) {
                    int t0 = __ldg(&g_csr_src[j + 4]); int t1 = __ldg(&g_csr_src[j + 5]);
                    int t2 = __ldg(&g_csr_src[j + 6]); int t3 = __ldg(&g_csr_src[j + 7]);
                    float4 v0 = __ldg(&h4[s0 * 32 + lane]);
                    float4 v1 = __ldg(&h4[s1 * 32 + lane]);
                    float4 v2 = __ldg(&h4[s2 * 32 + lane]);
                    float4 v3 = __ldg(&h4[s3 * 32 + lane]);
                    A0.x += v0.x; A0.y += v0.y; A0.z += v0.z; A0.w += v0.w;
                    A1.x += v1.x; A1.y += v1.y; A1.z += v1.z; A1.w += v1.w;
                    A2.x += v2.x; A2.y += v2.y; A2.z += v2.z; A2.w += v2.w;
                    A3.x += v3.x; A3.y += v3.y; A3.z += v3.z; A3.w += v3.w;
                    s0 = t0; s1 = t1; s2 = t2; s3 = t3;
                }
                if (have) {
                    float4 v0 = __ldg(&h4[s0 * 32 + lane]);
                    float4 v1 = __ldg(&h4[s1 * 32 + lane]);
                    float4 v2 = __ldg(&h4[s2 * 32 + lane]);
                    float4 v3 = __ldg(&h4[s3 * 32 + lane]);
                    A0.x += v0.x; A0.y += v0.y; A0.z += v0.z; A0.w += v0.w;
                    A1.x += v1.x; A1.y += v1.y; A1.z += v1.z; A1.w += v1.w;
                    A2.x += v2.x; A2.y += v2.y; A2.z += v2.z; A2.w += v2.w;
                    A3.x += v3.x; A3.y += v3.y; A3.z += v3.z; A3.w += v3.w;
                    j += 4;
                }
                for (; j < end; j++) {
                    int u = __ldg(&g_csr_src[j]);
                    float4 v0 = __ldg(&h4[u * 32 + lane]);
                    A0.x += v0.x; A0.y += v0.y; A0.z += v0.z; A0.w += v0.w;
                }
            }
            float dn = __ldg(&g_dst_norm[gw]);
            acc.x = ((A0.x + A1.x) + (A2.x + A3.x)) * dn;
            acc.y = ((A0.y + A1.y) + (A2.y + A3.y)) * dn;
            acc.z = ((A0.z + A1.z) + (A2.z + A3.z)) * dn;
            acc.w = ((A0.w + A1.w) + (A2.w + A3.w)) * dn;
        }
        // split to bf16 hi/lo, store to smem in ldmatrix layout
        __nv_bfloat16 hx = __float2bfloat16(acc.x), hy = __float2bfloat16(acc.y);
        __nv_bfloat16 hz = __float2bfloat16(acc.z), hw = __float2bfloat16(acc.w);
        ushort4 vh, vl;
        vh.x = __bfloat16_as_ushort(hx); vh.y = __bfloat16_as_ushort(hy);
        vh.z = __bfloat16_as_ushort(hz); vh.w = __bfloat16_as_ushort(hw);
        vl.x = __bfloat16_as_ushort(__float2bfloat16(acc.x - __bfloat162float(hx)));
        vl.y = __bfloat16_as_ushort(__float2bfloat16(acc.y - __bfloat162float(hy)));
        vl.z = __bfloat16_as_ushort(__float2bfloat16(acc.z - __bfloat162float(hz)));
        vl.w = __bfloat16_as_ushort(__float2bfloat16(acc.w - __bfloat162float(hw)));
        *(ushort4*)&sAh[r * LDA + lane * 4] = vh;
        *(ushort4*)&sAl[r * LDA + lane * 4] = vl;
    }
    __syncthreads();

    // ---------------- phase 2: 3-term mma, warp tile 32m x 16n ----------------
    int mw = w & 3, nw = w >> 2;     // 4 m-groups x 8 n-groups

    float acc2[2][2][4];
#pragma unroll
    for (int mt = 0; mt < 2; mt++)
#pragma unroll
        for (int nt = 0; nt < 2; nt++)
#pragma unroll
            for (int q = 0; q < 4; q++) acc2[mt][nt][q] = 0.f;

    unsigned aH[2], aL[2];
#pragma unroll
    for (int mt = 0; mt < 2; mt++) {
        int r = mw * 32 + mt * 16 + (lane & 15);
        aH[mt] = s2u(&sAh[r * LDA + (lane >> 4) * 8]);
        aL[mt] = s2u(&sAl[r * LDA + (lane >> 4) * 8]);
    }
    unsigned bB = (lane < 16) ? s2u(&sWh[(lane & 15) * LDA + nw * 16])
                              : s2u(&sWl[(lane & 15) * LDA + nw * 16]);

#pragma unroll
    for (int ks = 0; ks < 8; ks++) {
        unsigned ah[2][4], al[2][4];
#pragma unroll
        for (int mt = 0; mt < 2; mt++) {
            LDSM_X4(ah[mt], aH[mt] + ks * 32);
            LDSM_X4(al[mt], aL[mt] + ks * 32);
        }
#pragma unroll
        for (int nt = 0; nt < 2; nt++) {
            unsigned b[4];                 // b[0..1]=Wh frag, b[2..3]=Wl frag
            LDSM_X4T(b, bB + ks * 16 * LDA * 2 + nt * 16);
#pragma unroll
            for (int mt = 0; mt < 2; mt++) {
                MMA16816(acc2[mt][nt], ah[mt], b[0], b[1]);
                MMA16816(acc2[mt][nt], ah[mt], b[2], b[3]);
                MMA16816(acc2[mt][nt], al[mt], b[0], b[1]);
            }
        }
    }

    // epilogue (prescale by src_norm for non-final layers)
#pragma unroll
    for (int mt = 0; mt < 2; mt++) {
        int r0 = t * DD + mw * 32 + mt * 16 + (lane >> 2);
        int r1 = r0 + 8;
        float sn0 = 1.f, sn1 = 1.f;
        if (out_sel != 0) {
            if (r0 < NN) sn0 = __ldg(&g_src_norm[r0]);
            if (r1 < NN) sn1 = __ldg(&g_src_norm[r1]);
        }
#pragma unroll
        for (int nt = 0; nt < 2; nt++) {
            int col = nw * 16 + nt * 8 + (lane & 3) * 2;
            float2 bb = *(const float2*)&bias[col];
            if (r0 < NN) {
                float2 v; v.x = (acc2[mt][nt][0] + bb.x) * sn0; v.y = (acc2[mt][nt][1] + bb.y) * sn0;
                *(float2*)&out[(size_t)r0 * DD + col] = v;
            }
            if (r1 < NN) {
                float2 v; v.x = (acc2[mt][nt][2] + bb.x) * sn1; v.y = (acc2[mt][nt][3] + bb.y) * sn1;
                *(float2*)&out[(size_t)r1 * DD + col] = v;
            }
        }
    }
}

// ---------------- launch ----------------
extern "C" void kernel_launch(void* const* d_in, const int* in_sizes, int n_in,
                              void* d_out, int out_size) {
    const float* feat = (const float*)d_in[0];
    const int*   src  = (const int*)d_in[1];
    const int*   dst  = (const int*)d_in[2];
    const float* W    = (const float*)d_in[3];
    const float* b    = (const float*)d_in[4];
    float* out = (float*)d_out;

    cudaFuncSetAttribute(k_fused, cudaFuncAttributeMaxDynamicSharedMemorySize, FSMEM);

    const int TB = 256;
    k_count_w<<<(NE + TB - 1) / TB, TB>>>(src, dst, W);    // 0
    k_scan2<<<NSB, 1024>>>();                              // 1
    k_fill<<<(NE + TB - 1) / TB, TB>>>(src, dst);          // 2

    k_fused<<<NT, 1024, FSMEM>>>(feat, 0, 0, b + 0 * DD, nullptr, 1);   // 3 <-- profiled
    k_fused<<<NT, 1024, FSMEM>>>(nullptr, 1, 1, b + 1 * DD, nullptr, 2);
    k_fused<<<NT, 1024, FSMEM>>>(nullptr, 2, 2, b + 2 * DD, nullptr, 1);
    k_fused<<<NT, 1024, FSMEM>>>(nullptr, 1, 3, b + 3 * DD, out, 0);
}